// round 11
// baseline (speedup 1.0000x reference)
#include <cuda_runtime.h>
#include <cuda_fp16.h>
#include <cstdint>

#define NN 50000
#define NF 128
#define NE 500000
#define SCAN_BLKS ((NN + 255) / 256)   // 196

// ---------------- scratch ----------------
__device__ int g_cnt[NN];      // zero at module load; re-zeroed by k_scan3 each call
__device__ int g_off[NN + 1];
__device__ int g_cur[NN];
__device__ int g_elist[NE];
__device__ int g_bsum[SCAN_BLKS];
__device__ int g_boff[SCAN_BLKS];
__device__ uint4 g_x0h[NN * 32];       // [node][512B]: halves, batch0 feats 0..127, batch1 128..255
__device__ uint4 g_w0h[4096];          // w0 as fp16, row-major [128][256]
__device__ uint4 g_w1h[2048];          // w1 as fp16, row-major [128][128]

__device__ __forceinline__ uint32_t h2u(__half2 h) { return *(uint32_t*)&h; }
__device__ __forceinline__ __half2 u2h(uint32_t u) { return *(__half2*)&u; }

// ---------------- kernel 0a: x0 -> fp16 packed ----------------
__global__ void k_xconv(const float* __restrict__ x0) {
    int i = blockIdx.x * blockDim.x + threadIdx.x;   // NN*32 = 1.6M
    if (i >= NN * 32) return;
    int n = i >> 5;
    int l = i & 31;
    int b = l >> 4;
    int f0 = (l & 15) * 8;
    const float* src = x0 + (size_t)b * NN * NF + (size_t)n * NF + f0;
    float4 v0 = *(const float4*)(src);
    float4 v1 = *(const float4*)(src + 4);
    uint4 o;
    o.x = h2u(__floats2half2_rn(v0.x, v0.y));
    o.y = h2u(__floats2half2_rn(v0.z, v0.w));
    o.z = h2u(__floats2half2_rn(v1.x, v1.y));
    o.w = h2u(__floats2half2_rn(v1.z, v1.w));
    g_x0h[i] = o;
}

// ---------------- kernel 0b: weights -> fp16 ----------------
__global__ void k_wconv(const float* __restrict__ w0, const float* __restrict__ w1) {
    int i = blockIdx.x * blockDim.x + threadIdx.x;   // 4096 + 2048
    const float* src;
    uint4* dst;
    if (i < 4096) { src = w0 + i * 8; dst = &g_w0h[i]; }
    else if (i < 6144) { src = w1 + (i - 4096) * 8; dst = &g_w1h[i - 4096]; }
    else return;
    float4 v0 = *(const float4*)(src);
    float4 v1 = *(const float4*)(src + 4);
    uint4 o;
    o.x = h2u(__floats2half2_rn(v0.x, v0.y));
    o.y = h2u(__floats2half2_rn(v0.z, v0.w));
    o.z = h2u(__floats2half2_rn(v1.x, v1.y));
    o.w = h2u(__floats2half2_rn(v1.z, v1.w));
    *dst = o;
}

// ---------------- CSR build ----------------
__global__ void k_hist(const int* __restrict__ dst) {
    int e = blockIdx.x * blockDim.x + threadIdx.x;
    if (e < NE) atomicAdd(&g_cnt[dst[e]], 1);
}

__global__ void k_scan1() {
    __shared__ int red[256];
    int t = threadIdx.x;
    int i = blockIdx.x * 256 + t;
    red[t] = (i < NN) ? g_cnt[i] : 0;
    __syncthreads();
    #pragma unroll
    for (int d = 128; d > 0; d >>= 1) {
        if (t < d) red[t] += red[t + d];
        __syncthreads();
    }
    if (t == 0) g_bsum[blockIdx.x] = red[0];
}

__global__ void k_scan2() {
    __shared__ int s[256];
    int t = threadIdx.x;
    int v = (t < SCAN_BLKS) ? g_bsum[t] : 0;
    s[t] = v;
    __syncthreads();
    #pragma unroll
    for (int d = 1; d < 256; d <<= 1) {
        int u = (t >= d) ? s[t - d] : 0;
        __syncthreads();
        s[t] += u;
        __syncthreads();
    }
    if (t < SCAN_BLKS) g_boff[t] = s[t] - v;
    if (t == 255) g_off[NN] = s[255];
}

__global__ void k_scan3() {
    __shared__ int s[256];
    int t = threadIdx.x;
    int i = blockIdx.x * 256 + t;
    int v = (i < NN) ? g_cnt[i] : 0;
    s[t] = v;
    __syncthreads();
    #pragma unroll
    for (int d = 1; d < 256; d <<= 1) {
        int u = (t >= d) ? s[t - d] : 0;
        __syncthreads();
        s[t] += u;
        __syncthreads();
    }
    if (i < NN) {
        int off = g_boff[blockIdx.x] + s[t] - v;
        g_off[i] = off;
        g_cur[i] = off;
        g_cnt[i] = 0;
    }
}

__global__ void k_fill(const int* __restrict__ dst, const int* __restrict__ src) {
    int e = blockIdx.x * blockDim.x + threadIdx.x;
    if (e < NE) {
        int d = dst[e];
        int p = atomicAdd(&g_cur[d], 1);
        g_elist[p] = src[e];
    }
}

// ---------------- kernel: fused reduce + fp16 MMA MLP ----------------
#define THREADS 1024
#define NODES_PER_BLK 64
// halves strides, chosen so (stride/2 * gid + tig) mod 32 is a permutation:
#define XS_STRH 264        // 264/2=132 ≡ 4 (mod 32)
#define WB_STRH 136        // 136/2=68  ≡ 4 (mod 32)
#define XS_BYTES (128 * XS_STRH * 2)   // 67584
#define WB_BYTES (128 * WB_STRH * 2)   // 34816
#define SM_BYTES (XS_BYTES + WB_BYTES) // 102400

__device__ __forceinline__ void mma16(float d[4],
                                      uint32_t a0, uint32_t a1, uint32_t a2, uint32_t a3,
                                      uint32_t b0, uint32_t b1) {
    asm volatile(
        "mma.sync.aligned.m16n8k16.row.col.f32.f16.f16.f32 "
        "{%0,%1,%2,%3}, {%4,%5,%6,%7}, {%8,%9}, {%0,%1,%2,%3};\n"
        : "+f"(d[0]), "+f"(d[1]), "+f"(d[2]), "+f"(d[3])
        : "r"(a0), "r"(a1), "r"(a2), "r"(a3), "r"(b0), "r"(b1));
}

__global__ __launch_bounds__(THREADS, 1)
void k_main(const float* __restrict__ x0,
            const float* __restrict__ b0v,
            const float* __restrict__ b1v, float* __restrict__ out) {
    extern __shared__ char smem[];
    char* xs = smem;                   // [128 rows][XS_STRH halves]; later hs [128][WB_STRH]
    char* wb = smem + XS_BYTES;        // [128 cols][WB_STRH halves]
    char* hs = smem;

    const int t = threadIdx.x;
    const int warp = t >> 5;           // 0..31
    const int lane = t & 31;
    const int gid = lane >> 2;
    const int tig = lane & 3;
    const int node0 = blockIdx.x * NODES_PER_BLK;

    // ======== phase 1: gather + segment mean/max (fp16 in, fp32 sum, fp16 max) ========
    // lane l: batch b=l>>4, features f0=(l&15)*8 .. +8; one LDG.128 per edge covers both batches
    #pragma unroll
    for (int nn = 0; nn < 2; nn++) {
        int ln = warp * 2 + nn;         // local node 0..63
        int n = node0 + ln;
        float s[8];
        #pragma unroll
        for (int q = 0; q < 8; q++) s[q] = 0.f;
        __half2 mx0 = __floats2half2_rn(-65504.f, -65504.f);
        __half2 mx1 = mx0, mx2 = mx0, mx3 = mx0;
        int cnt = 1;
        if (n < NN) {
            int beg = g_off[n], end = g_off[n + 1];
            int deg = end - beg;
            bool has = deg > 0;
            cnt = has ? deg : 1;
            for (int ii = 0; ii < cnt; ii++) {
                int sidx = has ? g_elist[beg + ii] : n;
                uint4 v = g_x0h[(size_t)sidx * 32 + lane];
                __half2 h0 = u2h(v.x), h1 = u2h(v.y), h2 = u2h(v.z), h3 = u2h(v.w);
                mx0 = __hmax2(mx0, h0); mx1 = __hmax2(mx1, h1);
                mx2 = __hmax2(mx2, h2); mx3 = __hmax2(mx3, h3);
                float2 f0 = __half22float2(h0), f1 = __half22float2(h1);
                float2 f2 = __half22float2(h2), f3 = __half22float2(h3);
                s[0] += f0.x; s[1] += f0.y; s[2] += f1.x; s[3] += f1.y;
                s[4] += f2.x; s[5] += f2.y; s[6] += f3.x; s[7] += f3.y;
            }
        }
        float inv = 1.f / (float)cnt;
        uint4 mean4, max4;
        mean4.x = h2u(__floats2half2_rn(s[0] * inv, s[1] * inv));
        mean4.y = h2u(__floats2half2_rn(s[2] * inv, s[3] * inv));
        mean4.z = h2u(__floats2half2_rn(s[4] * inv, s[5] * inv));
        mean4.w = h2u(__floats2half2_rn(s[6] * inv, s[7] * inv));
        max4.x = h2u(mx0); max4.y = h2u(mx1); max4.z = h2u(mx2); max4.w = h2u(mx3);
        if (n >= NN) {
            mean4 = make_uint4(0, 0, 0, 0);
            max4 = make_uint4(0, 0, 0, 0);
        }
        int b = lane >> 4;
        int f0 = (lane & 15) * 8;
        int row = ln * 2 + b;
        *(uint4*)(xs + row * (XS_STRH * 2) + f0 * 2) = mean4;          // cols 0..127
        *(uint4*)(xs + row * (XS_STRH * 2) + 256 + f0 * 2) = max4;     // cols 128..255
    }

    // ======== warp tile mapping: 32 rows x 16 cols (4x8 warp grid) ========
    const int rg = warp >> 3;
    const int cg = warp & 7;
    const int mr = rg * 32;
    const int nc = cg * 16;

    // ======== GEMM1: h = relu(x @ w0^T + b0), K=256 in 2 chunks of 128 ========
    float d1[2][2][4];
    #pragma unroll
    for (int j = 0; j < 2; j++) {
        int c0 = nc + 8 * j + 2 * tig;
        float bb0 = b0v[c0], bb1 = b0v[c0 + 1];
        #pragma unroll
        for (int mi = 0; mi < 2; mi++) {
            d1[mi][j][0] = bb0; d1[mi][j][1] = bb1;
            d1[mi][j][2] = bb0; d1[mi][j][3] = bb1;
        }
    }

    #pragma unroll
    for (int kc = 0; kc < 2; kc++) {
        __syncthreads();
        // stage w0 chunk kc: [128 cols][128 k] fp16
        for (int i = t; i < 2048; i += THREADS) {
            int col = i >> 4, q = i & 15;
            *(uint4*)(wb + col * (WB_STRH * 2) + q * 16) = g_w0h[col * 32 + kc * 16 + q];
        }
        __syncthreads();

        #pragma unroll
        for (int ks = 0; ks < 8; ks++) {
            int kk = kc * 128 + ks * 16;
            int kl = ks * 16;
            uint32_t a[2][4], b[2][2];
            #pragma unroll
            for (int mi = 0; mi < 2; mi++) {
                int r0 = mr + mi * 16 + gid;
                const char* p0 = xs + r0 * (XS_STRH * 2) + (kk + 2 * tig) * 2;
                const char* p1 = xs + (r0 + 8) * (XS_STRH * 2) + (kk + 2 * tig) * 2;
                a[mi][0] = *(const uint32_t*)(p0);
                a[mi][1] = *(const uint32_t*)(p1);
                a[mi][2] = *(const uint32_t*)(p0 + 16);
                a[mi][3] = *(const uint32_t*)(p1 + 16);
            }
            #pragma unroll
            for (int j = 0; j < 2; j++) {
                int c = nc + 8 * j + gid;
                const char* p = wb + c * (WB_STRH * 2) + (kl + 2 * tig) * 2;
                b[j][0] = *(const uint32_t*)(p);
                b[j][1] = *(const uint32_t*)(p + 16);
            }
            #pragma unroll
            for (int mi = 0; mi < 2; mi++)
                #pragma unroll
                for (int j = 0; j < 2; j++)
                    mma16(d1[mi][j], a[mi][0], a[mi][1], a[mi][2], a[mi][3],
                          b[j][0], b[j][1]);
        }
    }

    __syncthreads();   // xs and wb fully consumed

    // store relu(h) fp16 into hs [128][WB_STRH]; stage w1 into wb
    #pragma unroll
    for (int mi = 0; mi < 2; mi++) {
        #pragma unroll
        for (int j = 0; j < 2; j++) {
            int r0 = mr + mi * 16 + gid;
            int c0 = nc + 8 * j + 2 * tig;
            __half2 lo = __floats2half2_rn(fmaxf(d1[mi][j][0], 0.f), fmaxf(d1[mi][j][1], 0.f));
            __half2 hi = __floats2half2_rn(fmaxf(d1[mi][j][2], 0.f), fmaxf(d1[mi][j][3], 0.f));
            *(uint32_t*)(hs + r0 * (WB_STRH * 2) + c0 * 2) = h2u(lo);
            *(uint32_t*)(hs + (r0 + 8) * (WB_STRH * 2) + c0 * 2) = h2u(hi);
        }
    }
    for (int i = t; i < 2048; i += THREADS) {
        int col = i >> 4, q = i & 15;
        *(uint4*)(wb + col * (WB_STRH * 2) + q * 16) = g_w1h[col * 16 + q];
    }
    __syncthreads();

    // ======== GEMM2: out = x0 + h @ w1^T + b1, K=128 ========
    float d2[2][2][4];
    #pragma unroll
    for (int j = 0; j < 2; j++) {
        int c0 = nc + 8 * j + 2 * tig;
        float bb0 = b1v[c0], bb1 = b1v[c0 + 1];
        #pragma unroll
        for (int mi = 0; mi < 2; mi++) {
            d2[mi][j][0] = bb0; d2[mi][j][1] = bb1;
            d2[mi][j][2] = bb0; d2[mi][j][3] = bb1;
        }
    }

    #pragma unroll
    for (int ks = 0; ks < 8; ks++) {
        int kk = ks * 16;
        uint32_t a[2][4], b[2][2];
        #pragma unroll
        for (int mi = 0; mi < 2; mi++) {
            int r0 = mr + mi * 16 + gid;
            const char* p0 = hs + r0 * (WB_STRH * 2) + (kk + 2 * tig) * 2;
            const char* p1 = hs + (r0 + 8) * (WB_STRH * 2) + (kk + 2 * tig) * 2;
            a[mi][0] = *(const uint32_t*)(p0);
            a[mi][1] = *(const uint32_t*)(p1);
            a[mi][2] = *(const uint32_t*)(p0 + 16);
            a[mi][3] = *(const uint32_t*)(p1 + 16);
        }
        #pragma unroll
        for (int j = 0; j < 2; j++) {
            int c = nc + 8 * j + gid;
            const char* p = wb + c * (WB_STRH * 2) + (kk + 2 * tig) * 2;
            b[j][0] = *(const uint32_t*)(p);
            b[j][1] = *(const uint32_t*)(p + 16);
        }
        #pragma unroll
        for (int mi = 0; mi < 2; mi++)
            #pragma unroll
            for (int j = 0; j < 2; j++)
                mma16(d2[mi][j], a[mi][0], a[mi][1], a[mi][2], a[mi][3],
                      b[j][0], b[j][1]);
    }

    // ======== epilogue: residual + store ========
    #pragma unroll
    for (int mi = 0; mi < 2; mi++) {
        #pragma unroll
        for (int j = 0; j < 2; j++) {
            int c0 = nc + 8 * j + 2 * tig;
            #pragma unroll
            for (int h = 0; h < 2; h++) {
                int r = mr + mi * 16 + gid + h * 8;
                int n = node0 + (r >> 1);
                if (n < NN) {
                    int b = r & 1;
                    int base = b * NN * NF + n * NF + c0;
                    float2 xv = *(const float2*)(x0 + base);
                    float2 o;
                    o.x = xv.x + d2[mi][j][h * 2 + 0];
                    o.y = xv.y + d2[mi][j][h * 2 + 1];
                    *(float2*)(out + base) = o;
                }
            }
        }
    }
}

// ---------------- launcher ----------------
extern "C" void kernel_launch(void* const* d_in, const int* in_sizes, int n_in,
                              void* d_out, int out_size) {
    const float* x0  = (const float*)d_in[0];
    const int*   dst = (const int*)d_in[1];
    const int*   src = (const int*)d_in[2];
    const float* w0  = (const float*)d_in[3];
    const float* b0  = (const float*)d_in[4];
    const float* w1  = (const float*)d_in[5];
    const float* b1  = (const float*)d_in[6];
    float* out = (float*)d_out;

    cudaFuncSetAttribute(k_main, cudaFuncAttributeMaxDynamicSharedMemorySize, SM_BYTES);

    k_xconv<<<(NN * 32 + 255) / 256, 256>>>(x0);
    k_wconv<<<(6144 + 255) / 256, 256>>>(w0, w1);
    k_hist<<<(NE + 255) / 256, 256>>>(dst);
    k_scan1<<<SCAN_BLKS, 256>>>();
    k_scan2<<<1, 256>>>();
    k_scan3<<<SCAN_BLKS, 256>>>();
    k_fill<<<(NE + 255) / 256, 256>>>(dst, src);

    int tiles = (NN + NODES_PER_BLK - 1) / NODES_PER_BLK;   // 782
    k_main<<<tiles, THREADS, SM_BYTES>>>(x0, b0, b1, out);
}

// round 12
// speedup vs baseline: 1.0528x; 1.0528x over previous
#include <cuda_runtime.h>
#include <cuda_fp16.h>
#include <cstdint>

#define NN 50000
#define NF 128
#define NE 500000
#define OFF_BLKS ((NN + 255) / 256)    // 196

// ---------------- scratch ----------------
__device__ int g_cnt[NN];      // zero at module load; re-zeroed by k_off each call
__device__ int g_off[NN];
__device__ int g_deg[NN];
__device__ int g_cur[NN];
__device__ int g_elist[NE];
__device__ int g_ctr;          // global range cursor; reset by k_pre each call
__device__ uint4 g_x0h[NN * 32];       // [node][512B]: fp16, batch0 feats 0..127, batch1 128..255
__device__ uint4 g_w0h[4096];          // w0 fp16 row-major [128][256]
__device__ uint4 g_w1h[2048];          // w1 fp16 row-major [128][128]

__device__ __forceinline__ uint32_t h2u(__half2 h) { return *(uint32_t*)&h; }
__device__ __forceinline__ __half2 u2h(uint32_t u) { return *(__half2*)&u; }

// ---------------- kernel 1: x conv + weight conv + degree hist + cursor reset ----------------
__global__ void k_pre(const float* __restrict__ x0, const int* __restrict__ dst,
                      const float* __restrict__ w0, const float* __restrict__ w1) {
    int i = blockIdx.x * blockDim.x + threadIdx.x;   // 1.6M threads
    if (i == 0) g_ctr = 0;
    if (i < NN * 32) {
        int n = i >> 5;
        int l = i & 31;
        int b = l >> 4;
        int f0 = (l & 15) * 8;
        const float* src = x0 + (size_t)b * NN * NF + (size_t)n * NF + f0;
        float4 v0 = *(const float4*)(src);
        float4 v1 = *(const float4*)(src + 4);
        uint4 o;
        o.x = h2u(__floats2half2_rn(v0.x, v0.y));
        o.y = h2u(__floats2half2_rn(v0.z, v0.w));
        o.z = h2u(__floats2half2_rn(v1.x, v1.y));
        o.w = h2u(__floats2half2_rn(v1.z, v1.w));
        g_x0h[i] = o;
    }
    if (i < NE) atomicAdd(&g_cnt[dst[i]], 1);
    if (i < 6144) {
        const float* src;
        uint4* dstp;
        if (i < 4096) { src = w0 + i * 8; dstp = &g_w0h[i]; }
        else          { src = w1 + (i - 4096) * 8; dstp = &g_w1h[i - 4096]; }
        float4 v0 = *(const float4*)(src);
        float4 v1 = *(const float4*)(src + 4);
        uint4 o;
        o.x = h2u(__floats2half2_rn(v0.x, v0.y));
        o.y = h2u(__floats2half2_rn(v0.z, v0.w));
        o.z = h2u(__floats2half2_rn(v1.x, v1.y));
        o.w = h2u(__floats2half2_rn(v1.z, v1.w));
        *dstp = o;
    }
}

// ---------------- kernel 2: range assignment (block scan + global cursor) ----------------
// CSR ranges need only be disjoint and sized by degree; node order is irrelevant
// because k_main reads [g_off[n], g_off[n]+g_deg[n]).
__global__ void k_off() {
    __shared__ int s[256];
    __shared__ int base;
    int t = threadIdx.x;
    int i = blockIdx.x * 256 + t;
    int v = (i < NN) ? g_cnt[i] : 0;
    s[t] = v;
    __syncthreads();
    #pragma unroll
    for (int d = 1; d < 256; d <<= 1) {
        int u = (t >= d) ? s[t - d] : 0;
        __syncthreads();
        s[t] += u;
        __syncthreads();
    }
    if (t == 255) base = atomicAdd(&g_ctr, s[255]);
    __syncthreads();
    if (i < NN) {
        int off = base + s[t] - v;    // exclusive prefix within block + block base
        g_off[i] = off;
        g_cur[i] = off;
        g_deg[i] = v;
        g_cnt[i] = 0;                 // restore invariant
    }
}

// ---------------- kernel 3: CSR fill ----------------
__global__ void k_fill(const int* __restrict__ dst, const int* __restrict__ src) {
    int e = blockIdx.x * blockDim.x + threadIdx.x;
    if (e < NE) {
        int d = dst[e];
        int p = atomicAdd(&g_cur[d], 1);
        g_elist[p] = src[e];
    }
}

// ---------------- kernel 4: fused reduce + fp16 MMA MLP ----------------
#define THREADS 1024
#define NODES_PER_BLK 64
#define XS_STRH 264        // halves; 132 ≡ 4 (mod 32) -> conflict-free fragment loads
#define WB_STRH 136        // halves; 68 ≡ 4 (mod 32)
#define XS_BYTES (128 * XS_STRH * 2)   // 67584
#define WB_BYTES (128 * WB_STRH * 2)   // 34816
#define SM_BYTES (XS_BYTES + WB_BYTES) // 102400

__device__ __forceinline__ void mma16(float d[4],
                                      uint32_t a0, uint32_t a1, uint32_t a2, uint32_t a3,
                                      uint32_t b0, uint32_t b1) {
    asm volatile(
        "mma.sync.aligned.m16n8k16.row.col.f32.f16.f16.f32 "
        "{%0,%1,%2,%3}, {%4,%5,%6,%7}, {%8,%9}, {%0,%1,%2,%3};\n"
        : "+f"(d[0]), "+f"(d[1]), "+f"(d[2]), "+f"(d[3])
        : "r"(a0), "r"(a1), "r"(a2), "r"(a3), "r"(b0), "r"(b1));
}

__global__ __launch_bounds__(THREADS, 1)
void k_main(const float* __restrict__ x0,
            const float* __restrict__ b0v,
            const float* __restrict__ b1v, float* __restrict__ out) {
    extern __shared__ char smem[];
    char* xs = smem;                   // [128 rows][XS_STRH halves]; later hs [128][WB_STRH]
    char* wb = smem + XS_BYTES;        // [128 cols][WB_STRH halves]
    char* hs = smem;

    const int t = threadIdx.x;
    const int warp = t >> 5;           // 0..31
    const int lane = t & 31;
    const int gid = lane >> 2;
    const int tig = lane & 3;
    const int node0 = blockIdx.x * NODES_PER_BLK;

    // ======== phase 1: gather + segment mean/max (fp16 in, fp32 sum, fp16 max) ========
    #pragma unroll
    for (int nn = 0; nn < 2; nn++) {
        int ln = warp * 2 + nn;         // local node 0..63
        int n = node0 + ln;
        float s[8];
        #pragma unroll
        for (int q = 0; q < 8; q++) s[q] = 0.f;
        __half2 mx0 = __floats2half2_rn(-65504.f, -65504.f);
        __half2 mx1 = mx0, mx2 = mx0, mx3 = mx0;
        int cnt = 1;
        if (n < NN) {
            int beg = g_off[n];
            int deg = g_deg[n];
            bool has = deg > 0;
            cnt = has ? deg : 1;
            for (int ii = 0; ii < cnt; ii++) {
                int sidx = has ? g_elist[beg + ii] : n;
                uint4 v = g_x0h[(size_t)sidx * 32 + lane];
                __half2 h0 = u2h(v.x), h1 = u2h(v.y), h2 = u2h(v.z), h3 = u2h(v.w);
                mx0 = __hmax2(mx0, h0); mx1 = __hmax2(mx1, h1);
                mx2 = __hmax2(mx2, h2); mx3 = __hmax2(mx3, h3);
                float2 f0 = __half22float2(h0), f1 = __half22float2(h1);
                float2 f2 = __half22float2(h2), f3 = __half22float2(h3);
                s[0] += f0.x; s[1] += f0.y; s[2] += f1.x; s[3] += f1.y;
                s[4] += f2.x; s[5] += f2.y; s[6] += f3.x; s[7] += f3.y;
            }
        }
        float inv = 1.f / (float)cnt;
        uint4 mean4, max4;
        mean4.x = h2u(__floats2half2_rn(s[0] * inv, s[1] * inv));
        mean4.y = h2u(__floats2half2_rn(s[2] * inv, s[3] * inv));
        mean4.z = h2u(__floats2half2_rn(s[4] * inv, s[5] * inv));
        mean4.w = h2u(__floats2half2_rn(s[6] * inv, s[7] * inv));
        max4.x = h2u(mx0); max4.y = h2u(mx1); max4.z = h2u(mx2); max4.w = h2u(mx3);
        if (n >= NN) {
            mean4 = make_uint4(0, 0, 0, 0);
            max4 = make_uint4(0, 0, 0, 0);
        }
        int b = lane >> 4;
        int f0 = (lane & 15) * 8;
        int row = ln * 2 + b;
        *(uint4*)(xs + row * (XS_STRH * 2) + f0 * 2) = mean4;          // cols 0..127
        *(uint4*)(xs + row * (XS_STRH * 2) + 256 + f0 * 2) = max4;     // cols 128..255
    }

    // ======== warp tile mapping: 32 rows x 16 cols (4x8 warp grid) ========
    const int rg = warp >> 3;
    const int cg = warp & 7;
    const int mr = rg * 32;
    const int nc = cg * 16;

    // ======== GEMM1: h = relu(x @ w0^T + b0), K=256 in 2 chunks of 128 ========
    float d1[2][2][4];
    #pragma unroll
    for (int j = 0; j < 2; j++) {
        int c0 = nc + 8 * j + 2 * tig;
        float bb0 = b0v[c0], bb1 = b0v[c0 + 1];
        #pragma unroll
        for (int mi = 0; mi < 2; mi++) {
            d1[mi][j][0] = bb0; d1[mi][j][1] = bb1;
            d1[mi][j][2] = bb0; d1[mi][j][3] = bb1;
        }
    }

    #pragma unroll
    for (int kc = 0; kc < 2; kc++) {
        __syncthreads();
        for (int i = t; i < 2048; i += THREADS) {
            int col = i >> 4, q = i & 15;
            *(uint4*)(wb + col * (WB_STRH * 2) + q * 16) = g_w0h[col * 32 + kc * 16 + q];
        }
        __syncthreads();

        #pragma unroll
        for (int ks = 0; ks < 8; ks++) {
            int kk = kc * 128 + ks * 16;
            int kl = ks * 16;
            uint32_t a[2][4], b[2][2];
            #pragma unroll
            for (int mi = 0; mi < 2; mi++) {
                int r0 = mr + mi * 16 + gid;
                const char* p0 = xs + r0 * (XS_STRH * 2) + (kk + 2 * tig) * 2;
                const char* p1 = xs + (r0 + 8) * (XS_STRH * 2) + (kk + 2 * tig) * 2;
                a[mi][0] = *(const uint32_t*)(p0);
                a[mi][1] = *(const uint32_t*)(p1);
                a[mi][2] = *(const uint32_t*)(p0 + 16);
                a[mi][3] = *(const uint32_t*)(p1 + 16);
            }
            #pragma unroll
            for (int j = 0; j < 2; j++) {
                int c = nc + 8 * j + gid;
                const char* p = wb + c * (WB_STRH * 2) + (kl + 2 * tig) * 2;
                b[j][0] = *(const uint32_t*)(p);
                b[j][1] = *(const uint32_t*)(p + 16);
            }
            #pragma unroll
            for (int mi = 0; mi < 2; mi++)
                #pragma unroll
                for (int j = 0; j < 2; j++)
                    mma16(d1[mi][j], a[mi][0], a[mi][1], a[mi][2], a[mi][3],
                          b[j][0], b[j][1]);
        }
    }

    __syncthreads();   // xs and wb fully consumed

    // store relu(h) fp16 into hs; stage w1 into wb
    #pragma unroll
    for (int mi = 0; mi < 2; mi++) {
        #pragma unroll
        for (int j = 0; j < 2; j++) {
            int r0 = mr + mi * 16 + gid;
            int c0 = nc + 8 * j + 2 * tig;
            __half2 lo = __floats2half2_rn(fmaxf(d1[mi][j][0], 0.f), fmaxf(d1[mi][j][1], 0.f));
            __half2 hi = __floats2half2_rn(fmaxf(d1[mi][j][2], 0.f), fmaxf(d1[mi][j][3], 0.f));
            *(uint32_t*)(hs + r0 * (WB_STRH * 2) + c0 * 2) = h2u(lo);
            *(uint32_t*)(hs + (r0 + 8) * (WB_STRH * 2) + c0 * 2) = h2u(hi);
        }
    }
    for (int i = t; i < 2048; i += THREADS) {
        int col = i >> 4, q = i & 15;
        *(uint4*)(wb + col * (WB_STRH * 2) + q * 16) = g_w1h[col * 16 + q];
    }
    __syncthreads();

    // ======== GEMM2: out = x0 + h @ w1^T + b1, K=128 ========
    float d2[2][2][4];
    #pragma unroll
    for (int j = 0; j < 2; j++) {
        int c0 = nc + 8 * j + 2 * tig;
        float bb0 = b1v[c0], bb1 = b1v[c0 + 1];
        #pragma unroll
        for (int mi = 0; mi < 2; mi++) {
            d2[mi][j][0] = bb0; d2[mi][j][1] = bb1;
            d2[mi][j][2] = bb0; d2[mi][j][3] = bb1;
        }
    }

    #pragma unroll
    for (int ks = 0; ks < 8; ks++) {
        int kk = ks * 16;
        uint32_t a[2][4], b[2][2];
        #pragma unroll
        for (int mi = 0; mi < 2; mi++) {
            int r0 = mr + mi * 16 + gid;
            const char* p0 = hs + r0 * (WB_STRH * 2) + (kk + 2 * tig) * 2;
            const char* p1 = hs + (r0 + 8) * (WB_STRH * 2) + (kk + 2 * tig) * 2;
            a[mi][0] = *(const uint32_t*)(p0);
            a[mi][1] = *(const uint32_t*)(p1);
            a[mi][2] = *(const uint32_t*)(p0 + 16);
            a[mi][3] = *(const uint32_t*)(p1 + 16);
        }
        #pragma unroll
        for (int j = 0; j < 2; j++) {
            int c = nc + 8 * j + gid;
            const char* p = wb + c * (WB_STRH * 2) + (kk + 2 * tig) * 2;
            b[j][0] = *(const uint32_t*)(p);
            b[j][1] = *(const uint32_t*)(p + 16);
        }
        #pragma unroll
        for (int mi = 0; mi < 2; mi++)
            #pragma unroll
            for (int j = 0; j < 2; j++)
                mma16(d2[mi][j], a[mi][0], a[mi][1], a[mi][2], a[mi][3],
                      b[j][0], b[j][1]);
    }

    // ======== epilogue: residual + store ========
    #pragma unroll
    for (int mi = 0; mi < 2; mi++) {
        #pragma unroll
        for (int j = 0; j < 2; j++) {
            int c0 = nc + 8 * j + 2 * tig;
            #pragma unroll
            for (int h = 0; h < 2; h++) {
                int r = mr + mi * 16 + gid + h * 8;
                int n = node0 + (r >> 1);
                if (n < NN) {
                    int b = r & 1;
                    int base = b * NN * NF + n * NF + c0;
                    float2 xv = *(const float2*)(x0 + base);
                    float2 o;
                    o.x = xv.x + d2[mi][j][h * 2 + 0];
                    o.y = xv.y + d2[mi][j][h * 2 + 1];
                    *(float2*)(out + base) = o;
                }
            }
        }
    }
}

// ---------------- launcher ----------------
extern "C" void kernel_launch(void* const* d_in, const int* in_sizes, int n_in,
                              void* d_out, int out_size) {
    const float* x0  = (const float*)d_in[0];
    const int*   dst = (const int*)d_in[1];
    const int*   src = (const int*)d_in[2];
    const float* w0  = (const float*)d_in[3];
    const float* b0  = (const float*)d_in[4];
    const float* w1  = (const float*)d_in[5];
    const float* b1  = (const float*)d_in[6];
    float* out = (float*)d_out;

    cudaFuncSetAttribute(k_main, cudaFuncAttributeMaxDynamicSharedMemorySize, SM_BYTES);

    k_pre<<<(NN * 32 + 255) / 256, 256>>>(x0, dst, w0, w1);
    k_off<<<OFF_BLKS, 256>>>();
    k_fill<<<(NE + 255) / 256, 256>>>(dst, src);

    int tiles = (NN + NODES_PER_BLK - 1) / NODES_PER_BLK;   // 782
    k_main<<<tiles, THREADS, SM_BYTES>>>(x0, b0, b1, out);
}

// round 13
// speedup vs baseline: 1.5223x; 1.4460x over previous
#include <cuda_runtime.h>
#include <cuda_fp16.h>
#include <cstdint>

#define NN 50000
#define NF 128
#define NE 500000
#define OFF_BLKS ((NN + 255) / 256)    // 196

// ---------------- scratch ----------------
__device__ int g_cnt[NN];      // zero at module load; re-zeroed by k_off each call
__device__ int g_off[NN];
__device__ int g_deg[NN];
__device__ int g_cur[NN];
__device__ int g_elist[NE];
__device__ int g_ctr;          // global range cursor; reset by k_pre each call
__device__ uint4 g_x0h[NN * 32];       // [node][512B]: fp16, batch0 feats 0..127, batch1 128..255
__device__ uint4 g_w0h[4096];          // w0 fp16 row-major [128][256]
__device__ uint4 g_w1h[2048];          // w1 fp16 row-major [128][128]

__device__ __forceinline__ uint32_t h2u(__half2 h) { return *(uint32_t*)&h; }
__device__ __forceinline__ __half2 u2h(uint32_t u) { return *(__half2*)&u; }

// ---------------- kernel 1: x conv + weight conv + degree hist + cursor reset ----------------
__global__ void k_pre(const float* __restrict__ x0, const int* __restrict__ dst,
                      const float* __restrict__ w0, const float* __restrict__ w1) {
    int i = blockIdx.x * blockDim.x + threadIdx.x;   // 1.6M threads
    if (i == 0) g_ctr = 0;
    if (i < NN * 32) {
        int n = i >> 5;
        int l = i & 31;
        int b = l >> 4;
        int f0 = (l & 15) * 8;
        const float* src = x0 + (size_t)b * NN * NF + (size_t)n * NF + f0;
        float4 v0 = *(const float4*)(src);
        float4 v1 = *(const float4*)(src + 4);
        uint4 o;
        o.x = h2u(__floats2half2_rn(v0.x, v0.y));
        o.y = h2u(__floats2half2_rn(v0.z, v0.w));
        o.z = h2u(__floats2half2_rn(v1.x, v1.y));
        o.w = h2u(__floats2half2_rn(v1.z, v1.w));
        g_x0h[i] = o;
    }
    if (i < NE) atomicAdd(&g_cnt[dst[i]], 1);
    if (i < 6144) {
        const float* src;
        uint4* dstp;
        if (i < 4096) { src = w0 + i * 8; dstp = &g_w0h[i]; }
        else          { src = w1 + (i - 4096) * 8; dstp = &g_w1h[i - 4096]; }
        float4 v0 = *(const float4*)(src);
        float4 v1 = *(const float4*)(src + 4);
        uint4 o;
        o.x = h2u(__floats2half2_rn(v0.x, v0.y));
        o.y = h2u(__floats2half2_rn(v0.z, v0.w));
        o.z = h2u(__floats2half2_rn(v1.x, v1.y));
        o.w = h2u(__floats2half2_rn(v1.z, v1.w));
        *dstp = o;
    }
}

// ---------------- kernel 2: range assignment (block scan + global cursor) ----------------
__global__ void k_off() {
    __shared__ int s[256];
    __shared__ int base;
    int t = threadIdx.x;
    int i = blockIdx.x * 256 + t;
    int v = (i < NN) ? g_cnt[i] : 0;
    s[t] = v;
    __syncthreads();
    #pragma unroll
    for (int d = 1; d < 256; d <<= 1) {
        int u = (t >= d) ? s[t - d] : 0;
        __syncthreads();
        s[t] += u;
        __syncthreads();
    }
    if (t == 255) base = atomicAdd(&g_ctr, s[255]);
    __syncthreads();
    if (i < NN) {
        int off = base + s[t] - v;
        g_off[i] = off;
        g_cur[i] = off;
        g_deg[i] = v;
        g_cnt[i] = 0;
    }
}

// ---------------- kernel 3: CSR fill ----------------
__global__ void k_fill(const int* __restrict__ dst, const int* __restrict__ src) {
    int e = blockIdx.x * blockDim.x + threadIdx.x;
    if (e < NE) {
        int d = dst[e];
        int p = atomicAdd(&g_cur[d], 1);
        g_elist[p] = src[e];
    }
}

// ---------------- kernel 4: fused reduce + fp16 MMA MLP ----------------
#define THREADS 1024
#define NODES_PER_BLK 64
#define XS_STRH 264        // halves; 132 ≡ 4 (mod 32) -> conflict-free fragment loads
#define WB_STRH 136        // halves; 68 ≡ 4 (mod 32)
#define XS_BYTES (128 * XS_STRH * 2)   // 67584
#define WB_BYTES (128 * WB_STRH * 2)   // 34816
#define SM_BYTES (XS_BYTES + WB_BYTES) // 102400

__device__ __forceinline__ void mma16(float d[4],
                                      uint32_t a0, uint32_t a1, uint32_t a2, uint32_t a3,
                                      uint32_t b0, uint32_t b1) {
    asm volatile(
        "mma.sync.aligned.m16n8k16.row.col.f32.f16.f16.f32 "
        "{%0,%1,%2,%3}, {%4,%5,%6,%7}, {%8,%9}, {%0,%1,%2,%3};\n"
        : "+f"(d[0]), "+f"(d[1]), "+f"(d[2]), "+f"(d[3])
        : "r"(a0), "r"(a1), "r"(a2), "r"(a3), "r"(b0), "r"(b1));
}

__global__ __launch_bounds__(THREADS, 1)
void k_main(const float* __restrict__ x0,
            const float* __restrict__ b0v,
            const float* __restrict__ b1v, float* __restrict__ out) {
    extern __shared__ char smem[];
    char* xs = smem;                   // [128 rows][XS_STRH halves]; later hs [128][WB_STRH]
    char* wb = smem + XS_BYTES;        // [128 cols][WB_STRH halves]
    char* hs = smem;

    const int t = threadIdx.x;
    const int warp = t >> 5;           // 0..31
    const int lane = t & 31;
    const int gid = lane >> 2;
    const int tig = lane & 3;
    const int node0 = blockIdx.x * NODES_PER_BLK;

    // ======== phase 1: gather + segment mean/max, packed fp16 HADD2/HMAX2 ========
    // two accumulator banks (alternate edges) -> halved dep chains, fp32 combine per node
    #pragma unroll
    for (int nn = 0; nn < 2; nn++) {
        int ln = warp * 2 + nn;         // local node 0..63
        int n = node0 + ln;
        const __half2 hz = __floats2half2_rn(0.f, 0.f);
        const __half2 hm = __floats2half2_rn(-65504.f, -65504.f);
        __half2 sA0 = hz, sA1 = hz, sA2 = hz, sA3 = hz;
        __half2 sB0 = hz, sB1 = hz, sB2 = hz, sB3 = hz;
        __half2 mA0 = hm, mA1 = hm, mA2 = hm, mA3 = hm;
        __half2 mB0 = hm, mB1 = hm, mB2 = hm, mB3 = hm;
        int cnt = 1;
        if (n < NN) {
            int beg = g_off[n];
            int deg = g_deg[n];
            bool has = deg > 0;
            cnt = has ? deg : 1;
            int ii = 0;
            for (; ii + 1 < cnt; ii += 2) {       // cnt>=2 implies has
                int e0 = g_elist[beg + ii];
                int e1 = g_elist[beg + ii + 1];
                uint4 v0 = g_x0h[(size_t)e0 * 32 + lane];
                uint4 v1 = g_x0h[(size_t)e1 * 32 + lane];
                __half2 a0 = u2h(v0.x), a1 = u2h(v0.y), a2 = u2h(v0.z), a3 = u2h(v0.w);
                __half2 b0 = u2h(v1.x), b1 = u2h(v1.y), b2 = u2h(v1.z), b3 = u2h(v1.w);
                sA0 = __hadd2(sA0, a0); sA1 = __hadd2(sA1, a1);
                sA2 = __hadd2(sA2, a2); sA3 = __hadd2(sA3, a3);
                sB0 = __hadd2(sB0, b0); sB1 = __hadd2(sB1, b1);
                sB2 = __hadd2(sB2, b2); sB3 = __hadd2(sB3, b3);
                mA0 = __hmax2(mA0, a0); mA1 = __hmax2(mA1, a1);
                mA2 = __hmax2(mA2, a2); mA3 = __hmax2(mA3, a3);
                mB0 = __hmax2(mB0, b0); mB1 = __hmax2(mB1, b1);
                mB2 = __hmax2(mB2, b2); mB3 = __hmax2(mB3, b3);
            }
            if (ii < cnt) {
                int e0 = has ? g_elist[beg + ii] : n;
                uint4 v0 = g_x0h[(size_t)e0 * 32 + lane];
                __half2 a0 = u2h(v0.x), a1 = u2h(v0.y), a2 = u2h(v0.z), a3 = u2h(v0.w);
                sA0 = __hadd2(sA0, a0); sA1 = __hadd2(sA1, a1);
                sA2 = __hadd2(sA2, a2); sA3 = __hadd2(sA3, a3);
                mA0 = __hmax2(mA0, a0); mA1 = __hmax2(mA1, a1);
                mA2 = __hmax2(mA2, a2); mA3 = __hmax2(mA3, a3);
            }
        }
        // combine banks in fp32, divide, repack
        float inv = 1.f / (float)cnt;
        float2 fa, fb;
        uint4 mean4, max4;
        fa = __half22float2(sA0); fb = __half22float2(sB0);
        mean4.x = h2u(__floats2half2_rn((fa.x + fb.x) * inv, (fa.y + fb.y) * inv));
        fa = __half22float2(sA1); fb = __half22float2(sB1);
        mean4.y = h2u(__floats2half2_rn((fa.x + fb.x) * inv, (fa.y + fb.y) * inv));
        fa = __half22float2(sA2); fb = __half22float2(sB2);
        mean4.z = h2u(__floats2half2_rn((fa.x + fb.x) * inv, (fa.y + fb.y) * inv));
        fa = __half22float2(sA3); fb = __half22float2(sB3);
        mean4.w = h2u(__floats2half2_rn((fa.x + fb.x) * inv, (fa.y + fb.y) * inv));
        max4.x = h2u(__hmax2(mA0, mB0));
        max4.y = h2u(__hmax2(mA1, mB1));
        max4.z = h2u(__hmax2(mA2, mB2));
        max4.w = h2u(__hmax2(mA3, mB3));
        if (n >= NN) {
            mean4 = make_uint4(0, 0, 0, 0);
            max4 = make_uint4(0, 0, 0, 0);
        }
        int b = lane >> 4;
        int f0 = (lane & 15) * 8;
        int row = ln * 2 + b;
        *(uint4*)(xs + row * (XS_STRH * 2) + f0 * 2) = mean4;          // cols 0..127
        *(uint4*)(xs + row * (XS_STRH * 2) + 256 + f0 * 2) = max4;     // cols 128..255
    }

    // ======== warp tile mapping: 32 rows x 16 cols (4x8 warp grid) ========
    const int rg = warp >> 3;
    const int cg = warp & 7;
    const int mr = rg * 32;
    const int nc = cg * 16;

    // ======== GEMM1: h = relu(x @ w0^T + b0), K=256 in 2 chunks of 128 ========
    float d1[2][2][4];
    #pragma unroll
    for (int j = 0; j < 2; j++) {
        int c0 = nc + 8 * j + 2 * tig;
        float bb0 = b0v[c0], bb1 = b0v[c0 + 1];
        #pragma unroll
        for (int mi = 0; mi < 2; mi++) {
            d1[mi][j][0] = bb0; d1[mi][j][1] = bb1;
            d1[mi][j][2] = bb0; d1[mi][j][3] = bb1;
        }
    }

    #pragma unroll
    for (int kc = 0; kc < 2; kc++) {
        __syncthreads();
        for (int i = t; i < 2048; i += THREADS) {
            int col = i >> 4, q = i & 15;
            *(uint4*)(wb + col * (WB_STRH * 2) + q * 16) = g_w0h[col * 32 + kc * 16 + q];
        }
        __syncthreads();

        #pragma unroll
        for (int ks = 0; ks < 8; ks++) {
            int kk = kc * 128 + ks * 16;
            int kl = ks * 16;
            uint32_t a[2][4], b[2][2];
            #pragma unroll
            for (int mi = 0; mi < 2; mi++) {
                int r0 = mr + mi * 16 + gid;
                const char* p0 = xs + r0 * (XS_STRH * 2) + (kk + 2 * tig) * 2;
                const char* p1 = xs + (r0 + 8) * (XS_STRH * 2) + (kk + 2 * tig) * 2;
                a[mi][0] = *(const uint32_t*)(p0);
                a[mi][1] = *(const uint32_t*)(p1);
                a[mi][2] = *(const uint32_t*)(p0 + 16);
                a[mi][3] = *(const uint32_t*)(p1 + 16);
            }
            #pragma unroll
            for (int j = 0; j < 2; j++) {
                int c = nc + 8 * j + gid;
                const char* p = wb + c * (WB_STRH * 2) + (kl + 2 * tig) * 2;
                b[j][0] = *(const uint32_t*)(p);
                b[j][1] = *(const uint32_t*)(p + 16);
            }
            #pragma unroll
            for (int mi = 0; mi < 2; mi++)
                #pragma unroll
                for (int j = 0; j < 2; j++)
                    mma16(d1[mi][j], a[mi][0], a[mi][1], a[mi][2], a[mi][3],
                          b[j][0], b[j][1]);
        }
    }

    __syncthreads();   // xs and wb fully consumed

    // store relu(h) fp16 into hs; stage w1 into wb
    #pragma unroll
    for (int mi = 0; mi < 2; mi++) {
        #pragma unroll
        for (int j = 0; j < 2; j++) {
            int r0 = mr + mi * 16 + gid;
            int c0 = nc + 8 * j + 2 * tig;
            __half2 lo = __floats2half2_rn(fmaxf(d1[mi][j][0], 0.f), fmaxf(d1[mi][j][1], 0.f));
            __half2 hi = __floats2half2_rn(fmaxf(d1[mi][j][2], 0.f), fmaxf(d1[mi][j][3], 0.f));
            *(uint32_t*)(hs + r0 * (WB_STRH * 2) + c0 * 2) = h2u(lo);
            *(uint32_t*)(hs + (r0 + 8) * (WB_STRH * 2) + c0 * 2) = h2u(hi);
        }
    }
    for (int i = t; i < 2048; i += THREADS) {
        int col = i >> 4, q = i & 15;
        *(uint4*)(wb + col * (WB_STRH * 2) + q * 16) = g_w1h[col * 16 + q];
    }
    __syncthreads();

    // ======== GEMM2: out = x0 + h @ w1^T + b1, K=128 ========
    float d2[2][2][4];
    #pragma unroll
    for (int j = 0; j < 2; j++) {
        int c0 = nc + 8 * j + 2 * tig;
        float bb0 = b1v[c0], bb1 = b1v[c0 + 1];
        #pragma unroll
        for (int mi = 0; mi < 2; mi++) {
            d2[mi][j][0] = bb0; d2[mi][j][1] = bb1;
            d2[mi][j][2] = bb0; d2[mi][j][3] = bb1;
        }
    }

    #pragma unroll
    for (int ks = 0; ks < 8; ks++) {
        int kk = ks * 16;
        uint32_t a[2][4], b[2][2];
        #pragma unroll
        for (int mi = 0; mi < 2; mi++) {
            int r0 = mr + mi * 16 + gid;
            const char* p0 = hs + r0 * (WB_STRH * 2) + (kk + 2 * tig) * 2;
            const char* p1 = hs + (r0 + 8) * (WB_STRH * 2) + (kk + 2 * tig) * 2;
            a[mi][0] = *(const uint32_t*)(p0);
            a[mi][1] = *(const uint32_t*)(p1);
            a[mi][2] = *(const uint32_t*)(p0 + 16);
            a[mi][3] = *(const uint32_t*)(p1 + 16);
        }
        #pragma unroll
        for (int j = 0; j < 2; j++) {
            int c = nc + 8 * j + gid;
            const char* p = wb + c * (WB_STRH * 2) + (kk + 2 * tig) * 2;
            b[j][0] = *(const uint32_t*)(p);
            b[j][1] = *(const uint32_t*)(p + 16);
        }
        #pragma unroll
        for (int mi = 0; mi < 2; mi++)
            #pragma unroll
            for (int j = 0; j < 2; j++)
                mma16(d2[mi][j], a[mi][0], a[mi][1], a[mi][2], a[mi][3],
                      b[j][0], b[j][1]);
    }

    // ======== epilogue: residual + store ========
    #pragma unroll
    for (int mi = 0; mi < 2; mi++) {
        #pragma unroll
        for (int j = 0; j < 2; j++) {
            int c0 = nc + 8 * j + 2 * tig;
            #pragma unroll
            for (int h = 0; h < 2; h++) {
                int r = mr + mi * 16 + gid + h * 8;
                int n = node0 + (r >> 1);
                if (n < NN) {
                    int b = r & 1;
                    int base = b * NN * NF + n * NF + c0;
                    float2 xv = *(const float2*)(x0 + base);
                    float2 o;
                    o.x = xv.x + d2[mi][j][h * 2 + 0];
                    o.y = xv.y + d2[mi][j][h * 2 + 1];
                    *(float2*)(out + base) = o;
                }
            }
        }
    }
}

// ---------------- launcher ----------------
extern "C" void kernel_launch(void* const* d_in, const int* in_sizes, int n_in,
                              void* d_out, int out_size) {
    const float* x0  = (const float*)d_in[0];
    const int*   dst = (const int*)d_in[1];
    const int*   src = (const int*)d_in[2];
    const float* w0  = (const float*)d_in[3];
    const float* b0  = (const float*)d_in[4];
    const float* w1  = (const float*)d_in[5];
    const float* b1  = (const float*)d_in[6];
    float* out = (float*)d_out;

    cudaFuncSetAttribute(k_main, cudaFuncAttributeMaxDynamicSharedMemorySize, SM_BYTES);

    k_pre<<<(NN * 32 + 255) / 256, 256>>>(x0, dst, w0, w1);
    k_off<<<OFF_BLKS, 256>>>();
    k_fill<<<(NE + 255) / 256, 256>>>(dst, src);

    int tiles = (NN + NODES_PER_BLK - 1) / NODES_PER_BLK;   // 782
    k_main<<<tiles, THREADS, SM_BYTES>>>(x0, b0, b1, out);
}

// round 16
// speedup vs baseline: 1.5700x; 1.0313x over previous
#include <cuda_runtime.h>
#include <cuda_fp16.h>
#include <cstdint>

#define NN 50000
#define NF 128
#define NE 500000
#define OFF_BLKS ((NN + 255) / 256)    // 196

// ---------------- scratch ----------------
__device__ int g_cnt[NN];      // zero at module load; re-zeroed by k_off each call
__device__ int g_off[NN];
__device__ int g_deg[NN];
__device__ int g_cur[NN];
__device__ int g_elist[NE];
__device__ int g_ctr;          // global range cursor; reset by k_pre each call
__device__ uint4 g_x0h[NN * 32];       // [node][512B]: fp16, batch0 feats 0..127, batch1 128..255
__device__ uint4 g_w0h[4096];          // w0 fp16 row-major [128][256]
__device__ uint4 g_w1h[2048];          // w1 fp16 row-major [128][128]

__device__ __forceinline__ uint32_t h2u(__half2 h) { return *(uint32_t*)&h; }
__device__ __forceinline__ __half2 u2h(uint32_t u) { return *(__half2*)&u; }

// ---------------- kernel 1: x conv + weight conv + degree hist + cursor reset ----------------
__global__ void k_pre(const float* __restrict__ x0, const int* __restrict__ dst,
                      const float* __restrict__ w0, const float* __restrict__ w1) {
    int i = blockIdx.x * blockDim.x + threadIdx.x;   // 1.6M threads
    if (i == 0) g_ctr = 0;
    if (i < NN * 32) {
        int n = i >> 5;
        int l = i & 31;
        int b = l >> 4;
        int f0 = (l & 15) * 8;
        const float* src = x0 + (size_t)b * NN * NF + (size_t)n * NF + f0;
        float4 v0 = *(const float4*)(src);
        float4 v1 = *(const float4*)(src + 4);
        uint4 o;
        o.x = h2u(__floats2half2_rn(v0.x, v0.y));
        o.y = h2u(__floats2half2_rn(v0.z, v0.w));
        o.z = h2u(__floats2half2_rn(v1.x, v1.y));
        o.w = h2u(__floats2half2_rn(v1.z, v1.w));
        g_x0h[i] = o;
    }
    if (i < NE) atomicAdd(&g_cnt[dst[i]], 1);
    if (i < 6144) {
        const float* src;
        uint4* dstp;
        if (i < 4096) { src = w0 + i * 8; dstp = &g_w0h[i]; }
        else          { src = w1 + (i - 4096) * 8; dstp = &g_w1h[i - 4096]; }
        float4 v0 = *(const float4*)(src);
        float4 v1 = *(const float4*)(src + 4);
        uint4 o;
        o.x = h2u(__floats2half2_rn(v0.x, v0.y));
        o.y = h2u(__floats2half2_rn(v0.z, v0.w));
        o.z = h2u(__floats2half2_rn(v1.x, v1.y));
        o.w = h2u(__floats2half2_rn(v1.z, v1.w));
        *dstp = o;
    }
}

// ---------------- kernel 2: range assignment (block scan + global cursor) ----------------
__global__ void k_off() {
    __shared__ int s[256];
    __shared__ int base;
    int t = threadIdx.x;
    int i = blockIdx.x * 256 + t;
    int v = (i < NN) ? g_cnt[i] : 0;
    s[t] = v;
    __syncthreads();
    #pragma unroll
    for (int d = 1; d < 256; d <<= 1) {
        int u = (t >= d) ? s[t - d] : 0;
        __syncthreads();
        s[t] += u;
        __syncthreads();
    }
    if (t == 255) base = atomicAdd(&g_ctr, s[255]);
    __syncthreads();
    if (i < NN) {
        int off = base + s[t] - v;
        g_off[i] = off;
        g_cur[i] = off;
        g_deg[i] = v;
        g_cnt[i] = 0;
    }
}

// ---------------- kernel 3: CSR fill ----------------
__global__ void k_fill(const int* __restrict__ dst, const int* __restrict__ src) {
    int e = blockIdx.x * blockDim.x + threadIdx.x;
    if (e < NE) {
        int d = dst[e];
        int p = atomicAdd(&g_cur[d], 1);
        g_elist[p] = src[e];
    }
}

// ---------------- kernel 4: fused reduce + fp16 MMA MLP ----------------
#define THREADS 1024
#define NODES_PER_BLK 64
#define XS_STRH 264        // halves; 132 ≡ 4 (mod 32) -> conflict-free
#define WB_STRH 136        // halves; 68 ≡ 4 (mod 32)
#define XS_STRB (XS_STRH * 2)          // 528 bytes
#define WB_STRB (WB_STRH * 2)          // 272 bytes
#define XS_BYTES (128 * XS_STRB)       // 67584
#define WB_BYTES (128 * WB_STRB)       // 34816
#define SM_BYTES (XS_BYTES + WB_BYTES) // 102400

__device__ __forceinline__ void mma16(float d[4],
                                      uint32_t a0, uint32_t a1, uint32_t a2, uint32_t a3,
                                      uint32_t b0, uint32_t b1) {
    asm volatile(
        "mma.sync.aligned.m16n8k16.row.col.f32.f16.f16.f32 "
        "{%0,%1,%2,%3}, {%4,%5,%6,%7}, {%8,%9}, {%0,%1,%2,%3};\n"
        : "+f"(d[0]), "+f"(d[1]), "+f"(d[2]), "+f"(d[3])
        : "r"(a0), "r"(a1), "r"(a2), "r"(a3), "r"(b0), "r"(b1));
}

__device__ __forceinline__ void ldsm4(uint32_t& r0, uint32_t& r1, uint32_t& r2, uint32_t& r3,
                                      uint32_t addr) {
    asm volatile("ldmatrix.sync.aligned.m8n8.x4.shared.b16 {%0,%1,%2,%3}, [%4];"
                 : "=r"(r0), "=r"(r1), "=r"(r2), "=r"(r3) : "r"(addr));
}

#define ACC_EDGE(su, mu, vv) do { \
    __half2 h0 = u2h((vv).x), h1 = u2h((vv).y), h2 = u2h((vv).z), h3 = u2h((vv).w); \
    su##0 = __hadd2(su##0, h0); su##1 = __hadd2(su##1, h1); \
    su##2 = __hadd2(su##2, h2); su##3 = __hadd2(su##3, h3); \
    mu##0 = __hmax2(mu##0, h0); mu##1 = __hmax2(mu##1, h1); \
    mu##2 = __hmax2(mu##2, h2); mu##3 = __hmax2(mu##3, h3); \
} while (0)

__global__ __launch_bounds__(THREADS, 1)
void k_main(const float* __restrict__ x0,
            const float* __restrict__ b0v,
            const float* __restrict__ b1v, float* __restrict__ out) {
    extern __shared__ char smem[];
    char* xs = smem;                   // [128 rows][XS_STRH halves]; later hs [128][WB_STRH]
    char* wb = smem + XS_BYTES;        // [128 cols][WB_STRH halves]
    char* hs = smem;

    const int t = threadIdx.x;
    const int warp = t >> 5;           // 0..31
    const int lane = t & 31;
    const int node0 = blockIdx.x * NODES_PER_BLK;

    // ======== phase 1: jammed dual-node gather (2 independent LDG chains) ========
    {
        int ln2 = warp * 2;
        int n0g = node0 + ln2, n1g = n0g + 1;
        bool ok0 = n0g < NN, ok1 = n1g < NN;
        int be0 = 0, dg0 = 0, be1 = 0, dg1 = 0;
        if (ok0) { be0 = g_off[n0g]; dg0 = g_deg[n0g]; }
        if (ok1) { be1 = g_off[n1g]; dg1 = g_deg[n1g]; }
        int c0 = ok0 ? (dg0 > 0 ? dg0 : 1) : 0;
        int c1 = ok1 ? (dg1 > 0 ? dg1 : 1) : 0;
        const __half2 hz = __floats2half2_rn(0.f, 0.f);
        const __half2 hmn = __floats2half2_rn(-65504.f, -65504.f);
        __half2 sa0 = hz, sa1 = hz, sa2 = hz, sa3 = hz;
        __half2 ma0 = hmn, ma1 = hmn, ma2 = hmn, ma3 = hmn;
        __half2 sb0 = hz, sb1 = hz, sb2 = hz, sb3 = hz;
        __half2 mb0 = hmn, mb1 = hmn, mb2 = hmn, mb3 = hmn;
        int cmin = c0 < c1 ? c0 : c1;
        for (int i = 0; i < cmin; i++) {
            int e0 = dg0 > 0 ? g_elist[be0 + i] : n0g;
            int e1 = dg1 > 0 ? g_elist[be1 + i] : n1g;
            uint4 v0 = g_x0h[(size_t)e0 * 32 + lane];
            uint4 v1 = g_x0h[(size_t)e1 * 32 + lane];
            ACC_EDGE(sa, ma, v0);
            ACC_EDGE(sb, mb, v1);
        }
        for (int i = cmin; i < c0; i++) {
            int e0 = dg0 > 0 ? g_elist[be0 + i] : n0g;
            uint4 v0 = g_x0h[(size_t)e0 * 32 + lane];
            ACC_EDGE(sa, ma, v0);
        }
        for (int i = cmin; i < c1; i++) {
            int e1 = dg1 > 0 ? g_elist[be1 + i] : n1g;
            uint4 v1 = g_x0h[(size_t)e1 * 32 + lane];
            ACC_EDGE(sb, mb, v1);
        }
        int b = lane >> 4;
        int f0 = (lane & 15) * 8;
        // node0
        {
            float inv = ok0 ? 1.f / (float)c0 : 0.f;
            float2 f;
            uint4 mean4, max4;
            f = __half22float2(sa0); mean4.x = h2u(__floats2half2_rn(f.x * inv, f.y * inv));
            f = __half22float2(sa1); mean4.y = h2u(__floats2half2_rn(f.x * inv, f.y * inv));
            f = __half22float2(sa2); mean4.z = h2u(__floats2half2_rn(f.x * inv, f.y * inv));
            f = __half22float2(sa3); mean4.w = h2u(__floats2half2_rn(f.x * inv, f.y * inv));
            max4.x = h2u(ma0); max4.y = h2u(ma1); max4.z = h2u(ma2); max4.w = h2u(ma3);
            if (!ok0) { mean4 = make_uint4(0, 0, 0, 0); max4 = make_uint4(0, 0, 0, 0); }
            int row = ln2 * 2 + b;
            *(uint4*)(xs + row * XS_STRB + f0 * 2) = mean4;
            *(uint4*)(xs + row * XS_STRB + 256 + f0 * 2) = max4;
        }
        // node1
        {
            float inv = ok1 ? 1.f / (float)c1 : 0.f;
            float2 f;
            uint4 mean4, max4;
            f = __half22float2(sb0); mean4.x = h2u(__floats2half2_rn(f.x * inv, f.y * inv));
            f = __half22float2(sb1); mean4.y = h2u(__floats2half2_rn(f.x * inv, f.y * inv));
            f = __half22float2(sb2); mean4.z = h2u(__floats2half2_rn(f.x * inv, f.y * inv));
            f = __half22float2(sb3); mean4.w = h2u(__floats2half2_rn(f.x * inv, f.y * inv));
            max4.x = h2u(mb0); max4.y = h2u(mb1); max4.z = h2u(mb2); max4.w = h2u(mb3);
            if (!ok1) { mean4 = make_uint4(0, 0, 0, 0); max4 = make_uint4(0, 0, 0, 0); }
            int row = (ln2 + 1) * 2 + b;
            *(uint4*)(xs + row * XS_STRB + f0 * 2) = mean4;
            *(uint4*)(xs + row * XS_STRB + 256 + f0 * 2) = max4;
        }
    }

    // ======== warp tile mapping: 32 rows x 16 cols (4x8 warp grid) ========
    const int rg = warp >> 3;
    const int cg = warp & 7;
    const int mr = rg * 32;
    const int nc = cg * 16;
    const int tig = lane & 3;

    // ldmatrix lane addressing
    const uint32_t xs_s = (uint32_t)__cvta_generic_to_shared(xs);
    const uint32_t wb_s = (uint32_t)__cvta_generic_to_shared(wb);
    const int arow = lane & 15;                       // row within 16-row A tile
    const int akof = (lane & 16) >> 1;                // 0 or 8 (k halves)
    const int brow = nc + ((lane & 16) >> 1) + (lane & 7);
    const int bkof = lane & 8;                        // 0 or 8 (k halves)
    const uint32_t aA0 = xs_s + (mr + arow) * XS_STRB + akof * 2;       // + kk*2
    const uint32_t aA1 = aA0 + 16 * XS_STRB;
    const uint32_t aB  = wb_s + brow * WB_STRB + bkof * 2;              // + kl*2
    const uint32_t hA0 = xs_s + (mr + arow) * WB_STRB + akof * 2;       // hs tile, + kk*2
    const uint32_t hA1 = hA0 + 16 * WB_STRB;

    // ======== GEMM1: h = relu(x @ w0^T + b0), K=256 in 2 chunks of 128 ========
    float d1[2][2][4];
    #pragma unroll
    for (int j = 0; j < 2; j++) {
        int c0 = nc + 8 * j + 2 * tig;
        float bb0 = b0v[c0], bb1 = b0v[c0 + 1];
        #pragma unroll
        for (int mi = 0; mi < 2; mi++) {
            d1[mi][j][0] = bb0; d1[mi][j][1] = bb1;
            d1[mi][j][2] = bb0; d1[mi][j][3] = bb1;
        }
    }

    #pragma unroll
    for (int kc = 0; kc < 2; kc++) {
        __syncthreads();
        for (int i = t; i < 2048; i += THREADS) {
            int col = i >> 4, q = i & 15;
            *(uint4*)(wb + col * WB_STRB + q * 16) = g_w0h[col * 32 + kc * 16 + q];
        }
        __syncthreads();

        #pragma unroll
        for (int ks = 0; ks < 8; ks++) {
            int kk = kc * 128 + ks * 16;
            int kl = ks * 16;
            uint32_t a[2][4], bb[4];
            ldsm4(a[0][0], a[0][1], a[0][2], a[0][3], aA0 + kk * 2);
            ldsm4(a[1][0], a[1][1], a[1][2], a[1][3], aA1 + kk * 2);
            ldsm4(bb[0], bb[1], bb[2], bb[3], aB + kl * 2);
            #pragma unroll
            for (int mi = 0; mi < 2; mi++) {
                mma16(d1[mi][0], a[mi][0], a[mi][1], a[mi][2], a[mi][3], bb[0], bb[1]);
                mma16(d1[mi][1], a[mi][0], a[mi][1], a[mi][2], a[mi][3], bb[2], bb[3]);
            }
        }
    }

    __syncthreads();   // xs and wb fully consumed

    // store relu(h) fp16 into hs; stage w1 into wb
    const int gid = lane >> 2;
    #pragma unroll
    for (int mi = 0; mi < 2; mi++) {
        #pragma unroll
        for (int j = 0; j < 2; j++) {
            int r0 = mr + mi * 16 + gid;
            int c0 = nc + 8 * j + 2 * tig;
            __half2 lo = __floats2half2_rn(fmaxf(d1[mi][j][0], 0.f), fmaxf(d1[mi][j][1], 0.f));
            __half2 hi = __floats2half2_rn(fmaxf(d1[mi][j][2], 0.f), fmaxf(d1[mi][j][3], 0.f));
            *(uint32_t*)(hs + r0 * WB_STRB + c0 * 2) = h2u(lo);
            *(uint32_t*)(hs + (r0 + 8) * WB_STRB + c0 * 2) = h2u(hi);
        }
    }
    for (int i = t; i < 2048; i += THREADS) {
        int col = i >> 4, q = i & 15;
        *(uint4*)(wb + col * WB_STRB + q * 16) = g_w1h[col * 16 + q];
    }
    __syncthreads();

    // ======== GEMM2: out = x0 + h @ w1^T + b1, K=128 ========
    float d2[2][2][4];
    #pragma unroll
    for (int j = 0; j < 2; j++) {
        int c0 = nc + 8 * j + 2 * tig;
        float bb0 = b1v[c0], bb1 = b1v[c0 + 1];
        #pragma unroll
        for (int mi = 0; mi < 2; mi++) {
            d2[mi][j][0] = bb0; d2[mi][j][1] = bb1;
            d2[mi][j][2] = bb0; d2[mi][j][3] = bb1;
        }
    }

    #pragma unroll
    for (int ks = 0; ks < 8; ks++) {
        int kk = ks * 16;
        uint32_t a[2][4], bb[4];
        ldsm4(a[0][0], a[0][1], a[0][2], a[0][3], hA0 + kk * 2);
        ldsm4(a[1][0], a[1][1], a[1][2], a[1][3], hA1 + kk * 2);
        ldsm4(bb[0], bb[1], bb[2], bb[3], aB + kk * 2);
        #pragma unroll
        for (int mi = 0; mi < 2; mi++) {
            mma16(d2[mi][0], a[mi][0], a[mi][1], a[mi][2], a[mi][3], bb[0], bb[1]);
            mma16(d2[mi][1], a[mi][0], a[mi][1], a[mi][2], a[mi][3], bb[2], bb[3]);
        }
    }

    // ======== epilogue: residual + store ========
    #pragma unroll
    for (int mi = 0; mi < 2; mi++) {
        #pragma unroll
        for (int j = 0; j < 2; j++) {
            int c0 = nc + 8 * j + 2 * tig;
            #pragma unroll
            for (int h = 0; h < 2; h++) {
                int r = mr + mi * 16 + gid + h * 8;
                int n = node0 + (r >> 1);
                if (n < NN) {
                    int b = r & 1;
                    int base = b * NN * NF + n * NF + c0;
                    float2 xv = *(const float2*)(x0 + base);
                    float2 o;
                    o.x = xv.x + d2[mi][j][h * 2 + 0];
                    o.y = xv.y + d2[mi][j][h * 2 + 1];
                    *(float2*)(out + base) = o;
                }
            }
        }
    }
}

// ---------------- launcher ----------------
extern "C" void kernel_launch(void* const* d_in, const int* in_sizes, int n_in,
                              void* d_out, int out_size) {
    const float* x0  = (const float*)d_in[0];
    const int*   dst = (const int*)d_in[1];
    const int*   src = (const int*)d_in[2];
    const float* w0  = (const float*)d_in[3];
    const float* b0  = (const float*)d_in[4];
    const float* w1  = (const float*)d_in[5];
    const float* b1  = (const float*)d_in[6];
    float* out = (float*)d_out;

    cudaFuncSetAttribute(k_main, cudaFuncAttributeMaxDynamicSharedMemorySize, SM_BYTES);

    k_pre<<<(NN * 32 + 255) / 256, 256>>>(x0, dst, w0, w1);
    k_off<<<OFF_BLKS, 256>>>();
    k_fill<<<(NE + 255) / 256, 256>>>(dst, src);

    int tiles = (NN + NODES_PER_BLK - 1) / NODES_PER_BLK;   // 782
    k_main<<<tiles, THREADS, SM_BYTES>>>(x0, b0, b1, out);
}